// round 11
// baseline (speedup 1.0000x reference)
#include <cuda_runtime.h>
#include <cuda_bf16.h>
#include <cstdint>

#define D        64
#define N_CAP    50048
#define E_CAP    1000448
#define BKT      128           // fixed bucket capacity per dst node
#define NB       96            // nodes per gemm block

// Scratch (static __device__ — no allocations allowed)
__device__ __align__(16) float  g_hW [N_CAP * D];            // fp32 h @ W^T
__device__ __align__(16) unsigned g_hWb[N_CAP * 32];         // bf16x2 hW/den (random gathers)
__device__ float  g_s1 [N_CAP];
__device__ float  g_s2 [N_CAP];
__device__ float  g_den[N_CAP];
__device__ int    g_cur[N_CAP];
__device__ __align__(16) float2 g_bkt[(size_t)N_CAP * BKT];  // (src bits, ex)

// bf16x2 bits -> two fp32 (exact widening, pure ALU ops)
__device__ __forceinline__ float2 bf2_to_f2(unsigned p) {
    return make_float2(__int_as_float(p << 16),
                       __int_as_float(p & 0xffff0000u));
}

// ---------------------------------------------------------------------------
// Kernel 1: hW = h @ W^T (fp32), s1/s2 via c = W^T a, zero den/cur.
// 96 nodes/block, 256 threads, 6 nodes x 4 feats register tile (round-8 best).
// ---------------------------------------------------------------------------
__global__ __launch_bounds__(256) void k_gemm(
    const float* __restrict__ h, const float* __restrict__ W,
    const float* __restrict__ a, int N)
{
    __shared__ float4 sh4[NB][17];        // h rows, 16 kq + 1 pad
    __shared__ float4 sA[16][4][16];      // sA[kq][jj][jg] = W[4jg+jj][4kq..+3]
    __shared__ float  sa[2 * D];
    __shared__ float4 sc1[16], sc2[16];   // c = W^T a, as float4 over k

    const int t  = threadIdx.x;
    const int jg = t & 15;
    const int ng = t >> 4;
    const int nbase = blockIdx.x * NB;

    const float4* h4 = reinterpret_cast<const float4*>(h);
    const float4* W4 = reinterpret_cast<const float4*>(W);

    #pragma unroll
    for (int r = 0; r < 6; ++r) {
        int idx  = t + 256 * r;            // 0..1535
        int node = idx >> 4;
        int kq   = idx & 15;
        int gn   = nbase + node;
        sh4[node][kq] = (gn < N) ? h4[gn * 16 + kq]
                                 : make_float4(0.f, 0.f, 0.f, 0.f);
    }
    #pragma unroll
    for (int r = 0; r < 4; ++r) {
        int idx = t + 256 * r;             // 0..1023
        int sjg = idx & 15;
        int sjj = (idx >> 4) & 3;
        int skq = idx >> 6;
        sA[skq][sjj][sjg] = W4[(4 * sjg + sjj) * 16 + skq];
    }
    if (t < 2 * D) sa[t] = a[t];
    __syncthreads();

    // Warps 0-1: c1/c2 from L1-resident global W
    if (t < D) {
        float c1 = 0.f, c2 = 0.f;
        #pragma unroll 16
        for (int j = 0; j < D; ++j) {
            float w = W[j * D + t];
            c1 = fmaf(w, sa[j],     c1);
            c2 = fmaf(w, sa[D + j], c2);
        }
        reinterpret_cast<float*>(sc1)[t] = c1;
        reinterpret_cast<float*>(sc2)[t] = c2;
    }

    float acc[6][4];
    #pragma unroll
    for (int i = 0; i < 6; ++i)
        #pragma unroll
        for (int jj = 0; jj < 4; ++jj) acc[i][jj] = 0.f;

    #pragma unroll 4
    for (int kq = 0; kq < 16; ++kq) {
        float4 w0 = sA[kq][0][jg];
        float4 w1 = sA[kq][1][jg];
        float4 w2 = sA[kq][2][jg];
        float4 w3 = sA[kq][3][jg];
        #pragma unroll
        for (int i = 0; i < 6; ++i) {
            float4 hv = sh4[ng + 16 * i][kq];   // broadcast (2 addrs/warp)
            acc[i][0] = fmaf(hv.x, w0.x, fmaf(hv.y, w0.y, fmaf(hv.z, w0.z, fmaf(hv.w, w0.w, acc[i][0]))));
            acc[i][1] = fmaf(hv.x, w1.x, fmaf(hv.y, w1.y, fmaf(hv.z, w1.z, fmaf(hv.w, w1.w, acc[i][1]))));
            acc[i][2] = fmaf(hv.x, w2.x, fmaf(hv.y, w2.y, fmaf(hv.z, w2.z, fmaf(hv.w, w2.w, acc[i][2]))));
            acc[i][3] = fmaf(hv.x, w3.x, fmaf(hv.y, w3.y, fmaf(hv.z, w3.z, fmaf(hv.w, w3.w, acc[i][3]))));
        }
    }

    float4* hW4 = reinterpret_cast<float4*>(g_hW);
    #pragma unroll
    for (int i = 0; i < 6; ++i) {
        int node = nbase + ng + 16 * i;
        if (node < N)
            hW4[node * 16 + jg] = make_float4(acc[i][0], acc[i][1], acc[i][2], acc[i][3]);
    }
    __syncthreads();   // sc1/sc2 ready

    // s1/s2 tail: one node per thread, float4 dots
    if (t < NB) {
        int node = nbase + t;
        if (node < N) {
            float s1 = 0.f, s2 = 0.f;
            #pragma unroll
            for (int kq = 0; kq < 16; ++kq) {
                float4 v  = sh4[t][kq];
                float4 c1 = sc1[kq], c2 = sc2[kq];
                s1 = fmaf(v.x, c1.x, fmaf(v.y, c1.y, fmaf(v.z, c1.z, fmaf(v.w, c1.w, s1))));
                s2 = fmaf(v.x, c2.x, fmaf(v.y, c2.y, fmaf(v.z, c2.z, fmaf(v.w, c2.w, s2))));
            }
            g_s1[node] = s1;
            g_s2[node] = s2;
            g_den[node] = 0.f;
            g_cur[node] = 0;
        }
    }
}

// ---------------------------------------------------------------------------
// Kernel 2 (single edge pass, 2 edges/thread via int2 loads):
//   ex = exp(leakyrelu(s1[src]+s2[dst]))   (values bounded ~|8|: no max-shift)
//   den[src] += ex;  bucket[dst] gets (src, ex)
// ---------------------------------------------------------------------------
__device__ __forceinline__ void edge_one(int s, int d)
{
    float v = g_s1[s] + g_s2[d];
    v = (v > 0.f) ? v : 0.2f * v;
    float ex = __expf(v);
    atomicAdd(&g_den[s], ex);
    int pos = atomicAdd(&g_cur[d], 1);
    if (pos < BKT)                     // safety guard (P(overflow) ~ 0)
        g_bkt[(size_t)d * BKT + pos] = make_float2(__int_as_float(s), ex);
}

__global__ __launch_bounds__(256) void k_edge(const int* __restrict__ ei, int E)
{
    int e0 = (blockIdx.x * 256 + threadIdx.x) * 2;
    if (e0 >= E) return;
    int2 ss = *reinterpret_cast<const int2*>(ei + e0);       // E even -> aligned
    int2 dd = *reinterpret_cast<const int2*>(ei + E + e0);
    edge_one(ss.x, dd.x);
    if (e0 + 1 < E) edge_one(ss.y, dd.y);
}

// ---------------------------------------------------------------------------
// Kernel 3: hWn[s] = hW[s] / den[s], bf16. One thread per (node, float4 chunk).
// ---------------------------------------------------------------------------
__global__ __launch_bounds__(256) void k_norm(int N)
{
    int idx  = blockIdx.x * 256 + threadIdx.x;
    int node = idx >> 4;
    int q    = idx & 15;
    if (node >= N) return;
    float rden = __frcp_rn(g_den[node]);     // broadcast across 16 threads
    float4 v = reinterpret_cast<const float4*>(g_hW)[node * 16 + q];
    __nv_bfloat162 b0 = __floats2bfloat162_rn(v.x * rden, v.y * rden);
    __nv_bfloat162 b1 = __floats2bfloat162_rn(v.z * rden, v.w * rden);
    uint2 packed;
    packed.x = *reinterpret_cast<unsigned*>(&b0);
    packed.y = *reinterpret_cast<unsigned*>(&b1);
    reinterpret_cast<uint2*>(g_hWb)[node * 16 + q] = packed;
}

// ---------------------------------------------------------------------------
// Kernel 4: gather + fused LayerNorm. One warp per dst node; float2 per lane.
// Unroll 16: all 16 gather loads issued before FMAs (MLP=16), float4 bucket
// reads (2 entries/load), bit-op bf16 converts, 4 accumulators.
// ---------------------------------------------------------------------------
__global__ __launch_bounds__(256) void k_gather_ln(
    const float* __restrict__ gamma, const float* __restrict__ beta,
    float* __restrict__ out, int N)
{
    int node = (blockIdx.x * 256 + threadIdx.x) >> 5;
    int lane = threadIdx.x & 31;
    if (node >= N) return;

    const float2* hw2 = reinterpret_cast<const float2*>(g_hW);
    float2 accA = hw2[node * 32 + lane];
    float2 accB = make_float2(0.f, 0.f);
    float2 accC = make_float2(0.f, 0.f);
    float2 accD = make_float2(0.f, 0.f);

    int cnt = g_cur[node];
    if (cnt > BKT) cnt = BKT;
    const float4* bkt4 = reinterpret_cast<const float4*>(g_bkt + (size_t)node * BKT);

    int i = 0;
    for (; i + 16 <= cnt; i += 16) {
        float4 q[8];
        #pragma unroll
        for (int u = 0; u < 8; ++u) q[u] = bkt4[(i >> 1) + u];

        unsigned ga[16];
        #pragma unroll
        for (int u = 0; u < 8; ++u) {
            ga[2*u]   = g_hWb[__float_as_int(q[u].x) * 32 + lane];
            ga[2*u+1] = g_hWb[__float_as_int(q[u].z) * 32 + lane];
        }
        #pragma unroll
        for (int u = 0; u < 8; ++u) {
            float2 v0 = bf2_to_f2(ga[2*u]);
            float2 v1 = bf2_to_f2(ga[2*u+1]);
            float2* aA = (u & 1) ? &accC : &accA;
            float2* aB = (u & 1) ? &accD : &accB;
            aA->x = fmaf(q[u].y, v0.x, aA->x);  aA->y = fmaf(q[u].y, v0.y, aA->y);
            aB->x = fmaf(q[u].w, v1.x, aB->x);  aB->y = fmaf(q[u].w, v1.y, aB->y);
        }
    }
    for (; i + 2 <= cnt; i += 2) {
        float4 qq = bkt4[i >> 1];
        float2 v0 = bf2_to_f2(g_hWb[__float_as_int(qq.x) * 32 + lane]);
        float2 v1 = bf2_to_f2(g_hWb[__float_as_int(qq.z) * 32 + lane]);
        accA.x = fmaf(qq.y, v0.x, accA.x);  accA.y = fmaf(qq.y, v0.y, accA.y);
        accB.x = fmaf(qq.w, v1.x, accB.x);  accB.y = fmaf(qq.w, v1.y, accB.y);
    }
    if (i < cnt) {
        float2 p = g_bkt[(size_t)node * BKT + i];
        float2 v = bf2_to_f2(g_hWb[__float_as_int(p.x) * 32 + lane]);
        accA.x = fmaf(p.y, v.x, accA.x);
        accA.y = fmaf(p.y, v.y, accA.y);
    }
    float2 acc = make_float2((accA.x + accB.x) + (accC.x + accD.x),
                             (accA.y + accB.y) + (accC.y + accD.y));

    // LayerNorm over the 64 values held by the warp
    float sum = acc.x + acc.y;
    float ss  = acc.x * acc.x + acc.y * acc.y;
    #pragma unroll
    for (int off = 16; off; off >>= 1) {
        sum += __shfl_xor_sync(0xFFFFFFFFu, sum, off);
        ss  += __shfl_xor_sync(0xFFFFFFFFu, ss,  off);
    }
    float mean = sum * (1.f / 64.f);
    float var  = ss * (1.f / 64.f) - mean * mean;
    float inv  = rsqrtf(var + 1e-5f);

    float2 gm = reinterpret_cast<const float2*>(gamma)[lane];
    float2 bt = reinterpret_cast<const float2*>(beta)[lane];
    float2 o;
    o.x = (acc.x - mean) * inv * gm.x + bt.x;
    o.y = (acc.y - mean) * inv * gm.y + bt.y;
    reinterpret_cast<float2*>(out)[node * 32 + lane] = o;
}

// ---------------------------------------------------------------------------
extern "C" void kernel_launch(void* const* d_in, const int* in_sizes, int n_in,
                              void* d_out, int out_size)
{
    const float* h     = (const float*)d_in[0];
    const int*   ei    = (const int*)  d_in[1];
    const float* W     = (const float*)d_in[2];
    const float* a     = (const float*)d_in[3];
    const float* gamma = (const float*)d_in[4];
    const float* beta  = (const float*)d_in[5];
    float*       out   = (float*)d_out;

    const int N = in_sizes[0] / D;
    const int E = in_sizes[1] / 2;

    k_gemm     <<<(N + NB - 1) / NB, 256>>>(h, W, a, N);
    k_edge     <<<(E / 2 + 255) / 256, 256>>>(ei, E);
    k_norm     <<<(N * 16 + 255) / 256, 256>>>(N);
    k_gather_ln<<<(N * 32 + 255) / 256, 256>>>(gamma, beta, out, N);
}

// round 12
// speedup vs baseline: 1.0902x; 1.0902x over previous
#include <cuda_runtime.h>
#include <cuda_bf16.h>
#include <cstdint>

#define D        64
#define N_CAP    50048
#define E_CAP    1000448
#define BKT      128           // fixed bucket capacity per dst node
#define NB       96            // nodes per gemm block

// Scratch (static __device__ — no allocations allowed)
__device__ __align__(16) float  g_hW [N_CAP * D];            // fp32 h @ W^T
__device__ __align__(8)  __nv_bfloat162 g_hWb[N_CAP * 32];   // bf16 hW/den (random gathers)
__device__ float  g_s1 [N_CAP];
__device__ float  g_s2 [N_CAP];
__device__ float  g_den[N_CAP];
__device__ int    g_cur[N_CAP];
__device__ __align__(8) float2 g_bkt[(size_t)N_CAP * BKT];   // (src bits, ex)

// ---------------------------------------------------------------------------
// Kernel 1: hW = h @ W^T (fp32), s1/s2 via c = W^T a, zero den/cur.
// 96 nodes/block, 256 threads, 6 nodes x 4 feats register tile (best measured).
// ---------------------------------------------------------------------------
__global__ __launch_bounds__(256) void k_gemm(
    const float* __restrict__ h, const float* __restrict__ W,
    const float* __restrict__ a, int N)
{
    __shared__ float4 sh4[NB][17];        // h rows, 16 kq + 1 pad
    __shared__ float4 sA[16][4][16];      // sA[kq][jj][jg] = W[4jg+jj][4kq..+3]
    __shared__ float  sa[2 * D];
    __shared__ float4 sc1[16], sc2[16];   // c = W^T a, as float4 over k

    const int t  = threadIdx.x;
    const int jg = t & 15;
    const int ng = t >> 4;
    const int nbase = blockIdx.x * NB;

    const float4* h4 = reinterpret_cast<const float4*>(h);
    const float4* W4 = reinterpret_cast<const float4*>(W);

    #pragma unroll
    for (int r = 0; r < 6; ++r) {
        int idx  = t + 256 * r;            // 0..1535
        int node = idx >> 4;
        int kq   = idx & 15;
        int gn   = nbase + node;
        sh4[node][kq] = (gn < N) ? h4[gn * 16 + kq]
                                 : make_float4(0.f, 0.f, 0.f, 0.f);
    }
    #pragma unroll
    for (int r = 0; r < 4; ++r) {
        int idx = t + 256 * r;             // 0..1023
        int sjg = idx & 15;
        int sjj = (idx >> 4) & 3;
        int skq = idx >> 6;
        sA[skq][sjj][sjg] = W4[(4 * sjg + sjj) * 16 + skq];
    }
    if (t < 2 * D) sa[t] = a[t];
    __syncthreads();

    // Warps 0-1: c1/c2 from L1-resident global W
    if (t < D) {
        float c1 = 0.f, c2 = 0.f;
        #pragma unroll 16
        for (int j = 0; j < D; ++j) {
            float w = W[j * D + t];
            c1 = fmaf(w, sa[j],     c1);
            c2 = fmaf(w, sa[D + j], c2);
        }
        reinterpret_cast<float*>(sc1)[t] = c1;
        reinterpret_cast<float*>(sc2)[t] = c2;
    }

    float acc[6][4];
    #pragma unroll
    for (int i = 0; i < 6; ++i)
        #pragma unroll
        for (int jj = 0; jj < 4; ++jj) acc[i][jj] = 0.f;

    #pragma unroll 4
    for (int kq = 0; kq < 16; ++kq) {
        float4 w0 = sA[kq][0][jg];
        float4 w1 = sA[kq][1][jg];
        float4 w2 = sA[kq][2][jg];
        float4 w3 = sA[kq][3][jg];
        #pragma unroll
        for (int i = 0; i < 6; ++i) {
            float4 hv = sh4[ng + 16 * i][kq];   // broadcast (2 addrs/warp)
            acc[i][0] = fmaf(hv.x, w0.x, fmaf(hv.y, w0.y, fmaf(hv.z, w0.z, fmaf(hv.w, w0.w, acc[i][0]))));
            acc[i][1] = fmaf(hv.x, w1.x, fmaf(hv.y, w1.y, fmaf(hv.z, w1.z, fmaf(hv.w, w1.w, acc[i][1]))));
            acc[i][2] = fmaf(hv.x, w2.x, fmaf(hv.y, w2.y, fmaf(hv.z, w2.z, fmaf(hv.w, w2.w, acc[i][2]))));
            acc[i][3] = fmaf(hv.x, w3.x, fmaf(hv.y, w3.y, fmaf(hv.z, w3.z, fmaf(hv.w, w3.w, acc[i][3]))));
        }
    }

    float4* hW4 = reinterpret_cast<float4*>(g_hW);
    #pragma unroll
    for (int i = 0; i < 6; ++i) {
        int node = nbase + ng + 16 * i;
        if (node < N)
            hW4[node * 16 + jg] = make_float4(acc[i][0], acc[i][1], acc[i][2], acc[i][3]);
    }
    __syncthreads();   // sc1/sc2 ready

    // s1/s2 tail: one node per thread, float4 dots
    if (t < NB) {
        int node = nbase + t;
        if (node < N) {
            float s1 = 0.f, s2 = 0.f;
            #pragma unroll
            for (int kq = 0; kq < 16; ++kq) {
                float4 v  = sh4[t][kq];
                float4 c1 = sc1[kq], c2 = sc2[kq];
                s1 = fmaf(v.x, c1.x, fmaf(v.y, c1.y, fmaf(v.z, c1.z, fmaf(v.w, c1.w, s1))));
                s2 = fmaf(v.x, c2.x, fmaf(v.y, c2.y, fmaf(v.z, c2.z, fmaf(v.w, c2.w, s2))));
            }
            g_s1[node] = s1;
            g_s2[node] = s2;
            g_den[node] = 0.f;
            g_cur[node] = 0;
        }
    }
}

// ---------------------------------------------------------------------------
// Kernel 2 (single edge pass, 2 edges/thread via int2 loads — proven -1.3us):
//   ex = exp(leakyrelu(s1[src]+s2[dst]))   (values bounded ~|8|: no max-shift)
//   den[src] += ex;  bucket[dst] gets (src, ex)
// ---------------------------------------------------------------------------
__device__ __forceinline__ void edge_one(int s, int d)
{
    float v = g_s1[s] + g_s2[d];
    v = (v > 0.f) ? v : 0.2f * v;
    float ex = __expf(v);
    atomicAdd(&g_den[s], ex);
    int pos = atomicAdd(&g_cur[d], 1);
    if (pos < BKT)                     // safety guard (P(overflow) ~ 0)
        g_bkt[(size_t)d * BKT + pos] = make_float2(__int_as_float(s), ex);
}

__global__ __launch_bounds__(256) void k_edge(const int* __restrict__ ei, int E)
{
    int e0 = (blockIdx.x * 256 + threadIdx.x) * 2;
    if (e0 >= E) return;
    int2 ss = *reinterpret_cast<const int2*>(ei + e0);       // E even -> aligned
    int2 dd = *reinterpret_cast<const int2*>(ei + E + e0);
    edge_one(ss.x, dd.x);
    if (e0 + 1 < E) edge_one(ss.y, dd.y);
}

// ---------------------------------------------------------------------------
// Kernel 3: hWn[s] = hW[s] / den[s], bf16. One thread per (node, float4 chunk).
// ---------------------------------------------------------------------------
__global__ __launch_bounds__(256) void k_norm(int N)
{
    int idx  = blockIdx.x * 256 + threadIdx.x;
    int node = idx >> 4;
    int q    = idx & 15;
    if (node >= N) return;
    float rden = __frcp_rn(g_den[node]);     // broadcast across 16 threads
    float4 v = reinterpret_cast<const float4*>(g_hW)[node * 16 + q];
    __nv_bfloat162 b0 = __floats2bfloat162_rn(v.x * rden, v.y * rden);
    __nv_bfloat162 b1 = __floats2bfloat162_rn(v.z * rden, v.w * rden);
    uint2 packed;
    packed.x = *reinterpret_cast<unsigned*>(&b0);
    packed.y = *reinterpret_cast<unsigned*>(&b1);
    reinterpret_cast<uint2*>(g_hWb)[node * 16 + q] = packed;
}

// ---------------------------------------------------------------------------
// Kernel 4: gather + fused LayerNorm (round-9 form: best measured 28.4us).
// One warp per dst node; float2 per lane; unroll 8, dual accumulators.
// ---------------------------------------------------------------------------
__global__ __launch_bounds__(256) void k_gather_ln(
    const float* __restrict__ gamma, const float* __restrict__ beta,
    float* __restrict__ out, int N)
{
    int node = (blockIdx.x * 256 + threadIdx.x) >> 5;
    int lane = threadIdx.x & 31;
    if (node >= N) return;

    const float2* hw2 = reinterpret_cast<const float2*>(g_hW);
    float2 accA = hw2[node * 32 + lane];
    float2 accB = make_float2(0.f, 0.f);

    int cnt = g_cur[node];
    if (cnt > BKT) cnt = BKT;
    const float2* bkt = g_bkt + (size_t)node * BKT;

    int i = 0;
    for (; i + 8 <= cnt; i += 8) {
        float2 p0 = bkt[i],     p1 = bkt[i + 1];
        float2 p2 = bkt[i + 2], p3 = bkt[i + 3];
        float2 p4 = bkt[i + 4], p5 = bkt[i + 5];
        float2 p6 = bkt[i + 6], p7 = bkt[i + 7];
        float2 v0 = __bfloat1622float2(g_hWb[__float_as_int(p0.x) * 32 + lane]);
        float2 v1 = __bfloat1622float2(g_hWb[__float_as_int(p1.x) * 32 + lane]);
        float2 v2 = __bfloat1622float2(g_hWb[__float_as_int(p2.x) * 32 + lane]);
        float2 v3 = __bfloat1622float2(g_hWb[__float_as_int(p3.x) * 32 + lane]);
        float2 v4 = __bfloat1622float2(g_hWb[__float_as_int(p4.x) * 32 + lane]);
        float2 v5 = __bfloat1622float2(g_hWb[__float_as_int(p5.x) * 32 + lane]);
        float2 v6 = __bfloat1622float2(g_hWb[__float_as_int(p6.x) * 32 + lane]);
        float2 v7 = __bfloat1622float2(g_hWb[__float_as_int(p7.x) * 32 + lane]);
        accA.x = fmaf(p0.y, v0.x, accA.x);  accA.y = fmaf(p0.y, v0.y, accA.y);
        accB.x = fmaf(p1.y, v1.x, accB.x);  accB.y = fmaf(p1.y, v1.y, accB.y);
        accA.x = fmaf(p2.y, v2.x, accA.x);  accA.y = fmaf(p2.y, v2.y, accA.y);
        accB.x = fmaf(p3.y, v3.x, accB.x);  accB.y = fmaf(p3.y, v3.y, accB.y);
        accA.x = fmaf(p4.y, v4.x, accA.x);  accA.y = fmaf(p4.y, v4.y, accA.y);
        accB.x = fmaf(p5.y, v5.x, accB.x);  accB.y = fmaf(p5.y, v5.y, accB.y);
        accA.x = fmaf(p6.y, v6.x, accA.x);  accA.y = fmaf(p6.y, v6.y, accA.y);
        accB.x = fmaf(p7.y, v7.x, accB.x);  accB.y = fmaf(p7.y, v7.y, accB.y);
    }
    for (; i < cnt; ++i) {
        float2 p = bkt[i];
        float2 v = __bfloat1622float2(g_hWb[__float_as_int(p.x) * 32 + lane]);
        accA.x = fmaf(p.y, v.x, accA.x);
        accA.y = fmaf(p.y, v.y, accA.y);
    }
    float2 acc = make_float2(accA.x + accB.x, accA.y + accB.y);

    // LayerNorm over the 64 values held by the warp
    float sum = acc.x + acc.y;
    float ss  = acc.x * acc.x + acc.y * acc.y;
    #pragma unroll
    for (int off = 16; off; off >>= 1) {
        sum += __shfl_xor_sync(0xFFFFFFFFu, sum, off);
        ss  += __shfl_xor_sync(0xFFFFFFFFu, ss,  off);
    }
    float mean = sum * (1.f / 64.f);
    float var  = ss * (1.f / 64.f) - mean * mean;
    float inv  = rsqrtf(var + 1e-5f);

    float2 gm = reinterpret_cast<const float2*>(gamma)[lane];
    float2 bt = reinterpret_cast<const float2*>(beta)[lane];
    float2 o;
    o.x = (acc.x - mean) * inv * gm.x + bt.x;
    o.y = (acc.y - mean) * inv * gm.y + bt.y;
    reinterpret_cast<float2*>(out)[node * 32 + lane] = o;
}

// ---------------------------------------------------------------------------
extern "C" void kernel_launch(void* const* d_in, const int* in_sizes, int n_in,
                              void* d_out, int out_size)
{
    const float* h     = (const float*)d_in[0];
    const int*   ei    = (const int*)  d_in[1];
    const float* W     = (const float*)d_in[2];
    const float* a     = (const float*)d_in[3];
    const float* gamma = (const float*)d_in[4];
    const float* beta  = (const float*)d_in[5];
    float*       out   = (float*)d_out;

    const int N = in_sizes[0] / D;
    const int E = in_sizes[1] / 2;

    k_gemm     <<<(N + NB - 1) / NB, 256>>>(h, W, a, N);
    k_edge     <<<(E / 2 + 255) / 256, 256>>>(ei, E);
    k_norm     <<<(N * 16 + 255) / 256, 256>>>(N);
    k_gather_ln<<<(N * 32 + 255) / 256, 256>>>(gamma, beta, out, N);
}

// round 13
// speedup vs baseline: 1.1395x; 1.0452x over previous
#include <cuda_runtime.h>
#include <cuda_bf16.h>
#include <cstdint>

#define D        64
#define N_CAP    50048
#define E_CAP    1000448
#define BKT      128           // fixed bucket capacity per dst node
#define NB       96            // nodes per gemm block

// Scratch (static __device__ — no allocations allowed)
__device__ __align__(16) float    g_hW [N_CAP * D];      // fp32 h @ W^T
__device__ __align__(16) unsigned g_hWb[N_CAP * 32];     // bf16x2 hW/den (random gathers)
__device__ float  g_s1 [N_CAP];
__device__ float  g_s2 [N_CAP];
__device__ float  g_den[N_CAP];
__device__ int    g_cur[N_CAP];
__device__ __align__(8) float2 g_bkt[(size_t)N_CAP * BKT];   // (src*16 bits, ex)

// bf16x2 bits -> two fp32 (exact widening, pure ALU)
__device__ __forceinline__ float2 bf2_to_f2(unsigned p) {
    return make_float2(__int_as_float(p << 16),
                       __int_as_float(p & 0xffff0000u));
}

// ---------------------------------------------------------------------------
// Kernel 1: hW = h @ W^T (fp32), s1/s2 via c = W^T a, zero den/cur.
// 96 nodes/block, 256 threads, 6 nodes x 4 feats register tile (best measured).
// ---------------------------------------------------------------------------
__global__ __launch_bounds__(256) void k_gemm(
    const float* __restrict__ h, const float* __restrict__ W,
    const float* __restrict__ a, int N)
{
    __shared__ float4 sh4[NB][17];        // h rows, 16 kq + 1 pad
    __shared__ float4 sA[16][4][16];      // sA[kq][jj][jg] = W[4jg+jj][4kq..+3]
    __shared__ float  sa[2 * D];
    __shared__ float4 sc1[16], sc2[16];   // c = W^T a, as float4 over k

    const int t  = threadIdx.x;
    const int jg = t & 15;
    const int ng = t >> 4;
    const int nbase = blockIdx.x * NB;

    const float4* h4 = reinterpret_cast<const float4*>(h);
    const float4* W4 = reinterpret_cast<const float4*>(W);

    #pragma unroll
    for (int r = 0; r < 6; ++r) {
        int idx  = t + 256 * r;            // 0..1535
        int node = idx >> 4;
        int kq   = idx & 15;
        int gn   = nbase + node;
        sh4[node][kq] = (gn < N) ? h4[gn * 16 + kq]
                                 : make_float4(0.f, 0.f, 0.f, 0.f);
    }
    #pragma unroll
    for (int r = 0; r < 4; ++r) {
        int idx = t + 256 * r;             // 0..1023
        int sjg = idx & 15;
        int sjj = (idx >> 4) & 3;
        int skq = idx >> 6;
        sA[skq][sjj][sjg] = W4[(4 * sjg + sjj) * 16 + skq];
    }
    if (t < 2 * D) sa[t] = a[t];
    __syncthreads();

    // Warps 0-1: c1/c2 from L1-resident global W
    if (t < D) {
        float c1 = 0.f, c2 = 0.f;
        #pragma unroll 16
        for (int j = 0; j < D; ++j) {
            float w = W[j * D + t];
            c1 = fmaf(w, sa[j],     c1);
            c2 = fmaf(w, sa[D + j], c2);
        }
        reinterpret_cast<float*>(sc1)[t] = c1;
        reinterpret_cast<float*>(sc2)[t] = c2;
    }

    float acc[6][4];
    #pragma unroll
    for (int i = 0; i < 6; ++i)
        #pragma unroll
        for (int jj = 0; jj < 4; ++jj) acc[i][jj] = 0.f;

    #pragma unroll 4
    for (int kq = 0; kq < 16; ++kq) {
        float4 w0 = sA[kq][0][jg];
        float4 w1 = sA[kq][1][jg];
        float4 w2 = sA[kq][2][jg];
        float4 w3 = sA[kq][3][jg];
        #pragma unroll
        for (int i = 0; i < 6; ++i) {
            float4 hv = sh4[ng + 16 * i][kq];   // broadcast (2 addrs/warp)
            acc[i][0] = fmaf(hv.x, w0.x, fmaf(hv.y, w0.y, fmaf(hv.z, w0.z, fmaf(hv.w, w0.w, acc[i][0]))));
            acc[i][1] = fmaf(hv.x, w1.x, fmaf(hv.y, w1.y, fmaf(hv.z, w1.z, fmaf(hv.w, w1.w, acc[i][1]))));
            acc[i][2] = fmaf(hv.x, w2.x, fmaf(hv.y, w2.y, fmaf(hv.z, w2.z, fmaf(hv.w, w2.w, acc[i][2]))));
            acc[i][3] = fmaf(hv.x, w3.x, fmaf(hv.y, w3.y, fmaf(hv.z, w3.z, fmaf(hv.w, w3.w, acc[i][3]))));
        }
    }

    float4* hW4 = reinterpret_cast<float4*>(g_hW);
    #pragma unroll
    for (int i = 0; i < 6; ++i) {
        int node = nbase + ng + 16 * i;
        if (node < N)
            hW4[node * 16 + jg] = make_float4(acc[i][0], acc[i][1], acc[i][2], acc[i][3]);
    }
    __syncthreads();   // sc1/sc2 ready

    // s1/s2 tail: one node per thread, float4 dots
    if (t < NB) {
        int node = nbase + t;
        if (node < N) {
            float s1 = 0.f, s2 = 0.f;
            #pragma unroll
            for (int kq = 0; kq < 16; ++kq) {
                float4 v  = sh4[t][kq];
                float4 c1 = sc1[kq], c2 = sc2[kq];
                s1 = fmaf(v.x, c1.x, fmaf(v.y, c1.y, fmaf(v.z, c1.z, fmaf(v.w, c1.w, s1))));
                s2 = fmaf(v.x, c2.x, fmaf(v.y, c2.y, fmaf(v.z, c2.z, fmaf(v.w, c2.w, s2))));
            }
            g_s1[node] = s1;
            g_s2[node] = s2;
            g_den[node] = 0.f;
            g_cur[node] = 0;
        }
    }
}

// ---------------------------------------------------------------------------
// Kernel 2 (single edge pass, 2 edges/thread via int2 loads):
//   ex = exp(leakyrelu(s1[src]+s2[dst]))   (values bounded ~|8|: no max-shift)
//   den[src] += ex;  bucket[dst] gets (src*16, ex)   [pre-scaled for gather]
// ---------------------------------------------------------------------------
__device__ __forceinline__ void edge_one(int s, int d)
{
    float v = g_s1[s] + g_s2[d];
    v = (v > 0.f) ? v : 0.2f * v;
    float ex = __expf(v);
    atomicAdd(&g_den[s], ex);
    int pos = atomicAdd(&g_cur[d], 1);
    if (pos < BKT)                     // safety guard (P(overflow) ~ 0)
        g_bkt[(size_t)d * BKT + pos] = make_float2(__int_as_float(s << 4), ex);
}

__global__ __launch_bounds__(256) void k_edge(const int* __restrict__ ei, int E)
{
    int e0 = (blockIdx.x * 256 + threadIdx.x) * 2;
    if (e0 >= E) return;
    int2 ss = *reinterpret_cast<const int2*>(ei + e0);       // E even -> aligned
    int2 dd = *reinterpret_cast<const int2*>(ei + E + e0);
    edge_one(ss.x, dd.x);
    if (e0 + 1 < E) edge_one(ss.y, dd.y);
}

// ---------------------------------------------------------------------------
// Kernel 3: hWn[s] = hW[s] / den[s], bf16. One thread per (node, float4 chunk).
// ---------------------------------------------------------------------------
__global__ __launch_bounds__(256) void k_norm(int N)
{
    int idx  = blockIdx.x * 256 + threadIdx.x;
    int node = idx >> 4;
    int q    = idx & 15;
    if (node >= N) return;
    float rden = __frcp_rn(g_den[node]);     // broadcast across 16 threads
    float4 v = reinterpret_cast<const float4*>(g_hW)[node * 16 + q];
    __nv_bfloat162 b0 = __floats2bfloat162_rn(v.x * rden, v.y * rden);
    __nv_bfloat162 b1 = __floats2bfloat162_rn(v.z * rden, v.w * rden);
    uint2 packed;
    packed.x = *reinterpret_cast<unsigned*>(&b0);
    packed.y = *reinterpret_cast<unsigned*>(&b1);
    reinterpret_cast<uint2*>(g_hWb)[node * 16 + q] = packed;
}

// ---------------------------------------------------------------------------
// Kernel 4: gather + fused LayerNorm. One warp per node, TWO edges in flight:
// each half-warp (16 lanes) handles one edge, uint2 (4 bf16) per lane — every
// warp instruction serves 2 edges. Halves take interleaved bucket entries
// (2u+half) of the SAME node -> no trip-count divergence; combined by one
// shfl_xor(16) at the end.
// ---------------------------------------------------------------------------
__global__ __launch_bounds__(256) void k_gather_ln(
    const float* __restrict__ gamma, const float* __restrict__ beta,
    float* __restrict__ out, int N)
{
    int node = (blockIdx.x * 256 + threadIdx.x) >> 5;
    int lane = threadIdx.x & 31;
    int half = lane >> 4;
    int hl   = lane & 15;
    if (node >= N) return;

    // acc = features [4hl .. 4hl+3]; half 0 seeded with fp32 self term
    float ax = 0.f, ay = 0.f, az = 0.f, aw = 0.f;
    if (half == 0) {
        float4 s = reinterpret_cast<const float4*>(g_hW)[node * 16 + hl];
        ax = s.x; ay = s.y; az = s.z; aw = s.w;
    }

    int cnt = g_cur[node];
    if (cnt > BKT) cnt = BKT;
    const float2* bkt  = g_bkt + (size_t)node * BKT;
    const uint2*  hwb2 = reinterpret_cast<const uint2*>(g_hWb);

    int base = 0;
    for (; base + 8 <= cnt; base += 8) {
        float2 p0 = bkt[base     + half];
        float2 p1 = bkt[base + 2 + half];
        float2 p2 = bkt[base + 4 + half];
        float2 p3 = bkt[base + 6 + half];
        uint2 q0 = hwb2[__float_as_int(p0.x) + hl];
        uint2 q1 = hwb2[__float_as_int(p1.x) + hl];
        uint2 q2 = hwb2[__float_as_int(p2.x) + hl];
        uint2 q3 = hwb2[__float_as_int(p3.x) + hl];
        {
            float2 lo = bf2_to_f2(q0.x), hi = bf2_to_f2(q0.y);
            ax = fmaf(p0.y, lo.x, ax);  ay = fmaf(p0.y, lo.y, ay);
            az = fmaf(p0.y, hi.x, az);  aw = fmaf(p0.y, hi.y, aw);
        }
        {
            float2 lo = bf2_to_f2(q1.x), hi = bf2_to_f2(q1.y);
            ax = fmaf(p1.y, lo.x, ax);  ay = fmaf(p1.y, lo.y, ay);
            az = fmaf(p1.y, hi.x, az);  aw = fmaf(p1.y, hi.y, aw);
        }
        {
            float2 lo = bf2_to_f2(q2.x), hi = bf2_to_f2(q2.y);
            ax = fmaf(p2.y, lo.x, ax);  ay = fmaf(p2.y, lo.y, ay);
            az = fmaf(p2.y, hi.x, az);  aw = fmaf(p2.y, hi.y, aw);
        }
        {
            float2 lo = bf2_to_f2(q3.x), hi = bf2_to_f2(q3.y);
            ax = fmaf(p3.y, lo.x, ax);  ay = fmaf(p3.y, lo.y, ay);
            az = fmaf(p3.y, hi.x, az);  aw = fmaf(p3.y, hi.y, aw);
        }
    }
    for (int e = base + half; e < cnt; e += 2) {
        float2 p = bkt[e];
        uint2  q = hwb2[__float_as_int(p.x) + hl];
        float2 lo = bf2_to_f2(q.x), hi = bf2_to_f2(q.y);
        ax = fmaf(p.y, lo.x, ax);  ay = fmaf(p.y, lo.y, ay);
        az = fmaf(p.y, hi.x, az);  aw = fmaf(p.y, hi.y, aw);
    }

    // combine the two halves (each lane pair hl / hl+16 holds same features)
    ax += __shfl_xor_sync(0xFFFFFFFFu, ax, 16);
    ay += __shfl_xor_sync(0xFFFFFFFFu, ay, 16);
    az += __shfl_xor_sync(0xFFFFFFFFu, az, 16);
    aw += __shfl_xor_sync(0xFFFFFFFFu, aw, 16);

    // LayerNorm over 64 values (16 lanes x 4 each; both halves redundant)
    float sum = (ax + ay) + (az + aw);
    float ss  = fmaf(ax, ax, fmaf(ay, ay, fmaf(az, az, aw * aw)));
    #pragma unroll
    for (int off = 8; off; off >>= 1) {
        sum += __shfl_xor_sync(0xFFFFFFFFu, sum, off);
        ss  += __shfl_xor_sync(0xFFFFFFFFu, ss,  off);
    }
    float mean = sum * (1.f / 64.f);
    float var  = ss * (1.f / 64.f) - mean * mean;
    float inv  = rsqrtf(var + 1e-5f);

    if (half == 0) {
        float4 gm = reinterpret_cast<const float4*>(gamma)[hl];
        float4 bt = reinterpret_cast<const float4*>(beta)[hl];
        float4 o;
        o.x = (ax - mean) * inv * gm.x + bt.x;
        o.y = (ay - mean) * inv * gm.y + bt.y;
        o.z = (az - mean) * inv * gm.z + bt.z;
        o.w = (aw - mean) * inv * gm.w + bt.w;
        reinterpret_cast<float4*>(out)[node * 16 + hl] = o;
    }
}

// ---------------------------------------------------------------------------
extern "C" void kernel_launch(void* const* d_in, const int* in_sizes, int n_in,
                              void* d_out, int out_size)
{
    const float* h     = (const float*)d_in[0];
    const int*   ei    = (const int*)  d_in[1];
    const float* W     = (const float*)d_in[2];
    const float* a     = (const float*)d_in[3];
    const float* gamma = (const float*)d_in[4];
    const float* beta  = (const float*)d_in[5];
    float*       out   = (float*)d_out;

    const int N = in_sizes[0] / D;
    const int E = in_sizes[1] / 2;

    k_gemm     <<<(N + NB - 1) / NB, 256>>>(h, W, a, N);
    k_edge     <<<(E / 2 + 255) / 256, 256>>>(ei, E);
    k_norm     <<<(N * 16 + 255) / 256, 256>>>(N);
    k_gather_ln<<<(N * 32 + 255) / 256, 256>>>(gamma, beta, out, N);
}